// round 3
// baseline (speedup 1.0000x reference)
#include <cuda_runtime.h>

namespace {
constexpr int H    = 8;
constexpr int NN   = 4096;
constexpr int FIN  = 512;
constexpr int HD   = 64;
constexpr int FOUT = 512;
constexpr int PK   = 68;    // stride for 64-wide tiles: 4-row fragment spacing = 272B (mod 128B = 16B) -> conflict-free
constexpr int PP   = 132;   // stride for 128-wide P/mask tile: 4*132*4B = 2112B mod 128 = 64B -> conflict-free fragments
}

// Scratch (allocation-free rule: __device__ globals)
__device__ __align__(16) float g_Q [H * NN * HD];
__device__ __align__(16) float g_K [H * NN * HD];
__device__ __align__(16) float g_V [H * NN * HD];
__device__ __align__(16) float g_Ho[H * NN * HD];

// ---------------------------------------------------------------------------
// Kernel 1: Q/K/V projection.  out[h,n,d] = sum_f X[h,n,f] * W[h,d,f]
// grid (NN/64, H, 3), block 256. 64x64 tile, 4x4 microtile, BK=32.
// ---------------------------------------------------------------------------
__global__ __launch_bounds__(256) void qkv_kernel(
    const float* __restrict__ X, const float* __restrict__ WQ,
    const float* __restrict__ WK, const float* __restrict__ WV) {
    __shared__ float Xs[64 * 36];
    __shared__ float Ws[64 * 36];
    const int nt = blockIdx.x, h = blockIdx.y, w = blockIdx.z;
    const float* Wm = (w == 0) ? WQ : (w == 1) ? WK : WV;
    float* out = (w == 0) ? g_Q : (w == 1) ? g_K : g_V;
    const int tid = threadIdx.x, tr = tid >> 4, tc = tid & 15;
    const float* Xp = X + ((size_t)h * NN + (size_t)nt * 64) * FIN;
    const float* Wp = Wm + (size_t)h * HD * FIN;
    float acc[4][4] = {};
    for (int k0 = 0; k0 < FIN; k0 += 32) {
        #pragma unroll
        for (int t = tid; t < 512; t += 256) {
            int r = t >> 3, k4 = (t & 7) * 4;
            *(float4*)&Xs[r * 36 + k4] = *(const float4*)&Xp[(size_t)r * FIN + k0 + k4];
            *(float4*)&Ws[r * 36 + k4] = *(const float4*)&Wp[(size_t)r * FIN + k0 + k4];
        }
        __syncthreads();
        #pragma unroll
        for (int kk = 0; kk < 32; kk += 4) {
            float a[4][4], b[4][4];
            #pragma unroll
            for (int i = 0; i < 4; i++) {
                float4 av = *(const float4*)&Xs[(tr * 4 + i) * 36 + kk];
                a[i][0] = av.x; a[i][1] = av.y; a[i][2] = av.z; a[i][3] = av.w;
                float4 bv = *(const float4*)&Ws[(tc * 4 + i) * 36 + kk];
                b[i][0] = bv.x; b[i][1] = bv.y; b[i][2] = bv.z; b[i][3] = bv.w;
            }
            #pragma unroll
            for (int u = 0; u < 4; u++)
                #pragma unroll
                for (int i = 0; i < 4; i++)
                    #pragma unroll
                    for (int j = 0; j < 4; j++)
                        acc[i][j] += a[i][u] * b[j][u];
        }
        __syncthreads();
    }
    float* op = out + ((size_t)h * NN + (size_t)nt * 64) * HD;
    #pragma unroll
    for (int i = 0; i < 4; i++)
        #pragma unroll
        for (int j = 0; j < 4; j++)
            op[(tr * 4 + i) * HD + tc * 4 + j] = acc[i][j];
}

// ---------------------------------------------------------------------------
// Kernel 2: flash attention, 128x128 score tile, 8x8 microtile (2x2 of 4x4),
// register-resident online softmax (16-lane shfl butterflies).
// grid (NN/128, H), block 256 (16x16 threads), ~173 KB dynamic smem, occ 1.
// Thread (tr,tc) owns S rows {tr*4+i, 64+tr*4+i} and cols {tc*4+j, 64+tc*4+j}.
// ---------------------------------------------------------------------------
__global__ __launch_bounds__(256, 1) void attn_kernel(const int* __restrict__ mask) {
    extern __shared__ float sm[];
    float* Qs  = sm;                 // [128][PK]
    float* Ks  = Qs + 128 * PK;      // [128][PK]
    float* Vs  = Ks + 128 * PK;      // [128][PK]
    float* Ps  = Vs + 128 * PK;      // [128][PP]  mask (int) then P (float)
    float* m_s = Ps + 128 * PP;      // [128]
    float* l_s = m_s + 128;          // [128]
    int*   Mi  = (int*)Ps;

    const int nt = blockIdx.x, h = blockIdx.y;
    const int tid = threadIdx.x, tr = tid >> 4, tc = tid & 15;
    const int r0l = tr * 4, r0h = 64 + tr * 4;          // owned row groups
    const int c0l = tc * 4, c0h = 64 + tc * 4;          // owned col groups

    // ---- load Q tile [128 x 64], fold in 1/sqrt(HD) = 0.125 ----
    const float* Qp = g_Q + ((size_t)h * NN + (size_t)nt * 128) * HD;
    #pragma unroll
    for (int u = 0; u < 8; u++) {
        int t = tid + u * 256, r = t >> 4, c4 = (t & 15) * 4;
        float4 v = *(const float4*)&Qp[r * HD + c4];
        v.x *= 0.125f; v.y *= 0.125f; v.z *= 0.125f; v.w *= 0.125f;
        *(float4*)&Qs[r * PK + c4] = v;
    }
    if (tid < 128) { m_s[tid] = -1e30f; l_s[tid] = 0.0f; }

    float o[8][4] = {};
    const int* mrow = mask + ((size_t)h * NN + (size_t)nt * 128) * NN;
    __syncthreads();

    for (int kv0 = 0; kv0 < NN; kv0 += 128) {
        // ---- stage K, V tiles and mask tile (mask into Ps region as ints) ----
        const float* Kp = g_K + ((size_t)h * NN + kv0) * HD;
        const float* Vp = g_V + ((size_t)h * NN + kv0) * HD;
        #pragma unroll
        for (int u = 0; u < 8; u++) {
            int t = tid + u * 256, r = t >> 4, c4 = (t & 15) * 4;
            *(float4*)&Ks[r * PK + c4] = *(const float4*)&Kp[r * HD + c4];
            *(float4*)&Vs[r * PK + c4] = *(const float4*)&Vp[r * HD + c4];
        }
        #pragma unroll
        for (int u = 0; u < 16; u++) {
            int t = tid + u * 256, r = t >> 5, c4 = (t & 31) * 4;
            *(int4*)&Mi[r * PP + c4] = *(const int4*)&mrow[(size_t)r * NN + kv0 + c4];
        }
        __syncthreads();

        // ---- S = Q K^T  (8x8 per thread as 2x2 blocks of 4x4) ----
        float s[8][8] = {};
        #pragma unroll
        for (int k = 0; k < HD; k += 4) {
            float a[8][4], b[8][4];
            #pragma unroll
            for (int i = 0; i < 4; i++) {
                float4 v;
                v = *(const float4*)&Qs[(r0l + i) * PK + k];
                a[i][0] = v.x; a[i][1] = v.y; a[i][2] = v.z; a[i][3] = v.w;
                v = *(const float4*)&Qs[(r0h + i) * PK + k];
                a[4 + i][0] = v.x; a[4 + i][1] = v.y; a[4 + i][2] = v.z; a[4 + i][3] = v.w;
                v = *(const float4*)&Ks[(c0l + i) * PK + k];
                b[i][0] = v.x; b[i][1] = v.y; b[i][2] = v.z; b[i][3] = v.w;
                v = *(const float4*)&Ks[(c0h + i) * PK + k];
                b[4 + i][0] = v.x; b[4 + i][1] = v.y; b[4 + i][2] = v.z; b[4 + i][3] = v.w;
            }
            #pragma unroll
            for (int u = 0; u < 4; u++)
                #pragma unroll
                for (int i = 0; i < 8; i++)
                    #pragma unroll
                    for (int j = 0; j < 8; j++)
                        s[i][j] += a[i][u] * b[j][u];
        }

        // ---- apply mask (each thread reads only its own staged cells) ----
        #pragma unroll
        for (int i = 0; i < 8; i++) {
            int r = (i < 4) ? (r0l + i) : (r0h + i - 4);
            int4 mL = *(const int4*)&Mi[r * PP + c0l];
            int4 mH = *(const int4*)&Mi[r * PP + c0h];
            if (mL.x == 0) s[i][0] = -1e30f;
            if (mL.y == 0) s[i][1] = -1e30f;
            if (mL.z == 0) s[i][2] = -1e30f;
            if (mL.w == 0) s[i][3] = -1e30f;
            if (mH.x == 0) s[i][4] = -1e30f;
            if (mH.y == 0) s[i][5] = -1e30f;
            if (mH.z == 0) s[i][6] = -1e30f;
            if (mH.w == 0) s[i][7] = -1e30f;
        }

        // ---- online softmax in registers; row spread over 16 lanes (same half-warp) ----
        #pragma unroll
        for (int i = 0; i < 8; i++) {
            int r = (i < 4) ? (r0l + i) : (r0h + i - 4);
            float mx = s[i][0];
            #pragma unroll
            for (int j = 1; j < 8; j++) mx = fmaxf(mx, s[i][j]);
            mx = fmaxf(mx, __shfl_xor_sync(0xffffffffu, mx, 1));
            mx = fmaxf(mx, __shfl_xor_sync(0xffffffffu, mx, 2));
            mx = fmaxf(mx, __shfl_xor_sync(0xffffffffu, mx, 4));
            mx = fmaxf(mx, __shfl_xor_sync(0xffffffffu, mx, 8));
            float mold = m_s[r];
            float mnew = fmaxf(mold, mx);
            float sum = 0.0f;
            #pragma unroll
            for (int j = 0; j < 8; j++) {
                float p = __expf(s[i][j] - mnew);
                s[i][j] = p;
                sum += p;
            }
            sum += __shfl_xor_sync(0xffffffffu, sum, 1);
            sum += __shfl_xor_sync(0xffffffffu, sum, 2);
            sum += __shfl_xor_sync(0xffffffffu, sum, 4);
            sum += __shfl_xor_sync(0xffffffffu, sum, 8);
            float scale = __expf(mold - mnew);
            if (tc == 0) {
                l_s[r] = l_s[r] * scale + sum;
                m_s[r] = mnew;
            }
            // rescale O accumulator rows in-register (scale known to all lanes)
            #pragma unroll
            for (int d = 0; d < 4; d++) o[i][d] *= scale;
        }

        // ---- write P (overwrites own mask cells only) ----
        #pragma unroll
        for (int i = 0; i < 8; i++) {
            int r = (i < 4) ? (r0l + i) : (r0h + i - 4);
            *(float4*)&Ps[r * PP + c0l] = make_float4(s[i][0], s[i][1], s[i][2], s[i][3]);
            *(float4*)&Ps[r * PP + c0h] = make_float4(s[i][4], s[i][5], s[i][6], s[i][7]);
        }
        __syncthreads();   // P visible; K/V/mask reads all complete

        // ---- O += P @ V  (thread: own 8 rows x cols tc*4..+4) ----
        #pragma unroll 4
        for (int k = 0; k < 128; k += 4) {
            float p[8][4], v[4][4];
            #pragma unroll
            for (int i = 0; i < 4; i++) {
                float4 pv;
                pv = *(const float4*)&Ps[(r0l + i) * PP + k];
                p[i][0] = pv.x; p[i][1] = pv.y; p[i][2] = pv.z; p[i][3] = pv.w;
                pv = *(const float4*)&Ps[(r0h + i) * PP + k];
                p[4 + i][0] = pv.x; p[4 + i][1] = pv.y; p[4 + i][2] = pv.z; p[4 + i][3] = pv.w;
            }
            #pragma unroll
            for (int u = 0; u < 4; u++) {
                float4 vv = *(const float4*)&Vs[(k + u) * PK + c0l];
                v[u][0] = vv.x; v[u][1] = vv.y; v[u][2] = vv.z; v[u][3] = vv.w;
            }
            #pragma unroll
            for (int u = 0; u < 4; u++)
                #pragma unroll
                for (int i = 0; i < 8; i++)
                    #pragma unroll
                    for (int d = 0; d < 4; d++)
                        o[i][d] += p[i][u] * v[u][d];
        }
        __syncthreads();   // protect Ks/Vs/Ps before next iteration's staging
    }

    // ---- finalize: divide by l, write Hout ----
    float* Op = g_Ho + ((size_t)h * NN + (size_t)nt * 128) * HD;
    #pragma unroll
    for (int i = 0; i < 8; i++) {
        int r = (i < 4) ? (r0l + i) : (r0h + i - 4);
        float linv = 1.0f / l_s[r];
        *(float4*)&Op[r * HD + c0l] =
            make_float4(o[i][0] * linv, o[i][1] * linv, o[i][2] * linv, o[i][3] * linv);
    }
}

// ---------------------------------------------------------------------------
// Kernel 3: output projection. out[n,fo] = sum_{h,d} Ho[h,n,d] * WO[fo, h*64+d]
// grid (NN/64, FOUT/64), block 256.
// ---------------------------------------------------------------------------
__global__ __launch_bounds__(256) void oproj_kernel(
    const float* __restrict__ WO, float* __restrict__ out) {
    __shared__ float As[64 * 36];
    __shared__ float Ws[64 * 36];
    const int nt = blockIdx.x, ft = blockIdx.y;
    const int tid = threadIdx.x, tr = tid >> 4, tc = tid & 15;
    float acc[4][4] = {};
    for (int k0 = 0; k0 < H * HD; k0 += 32) {
        const int hh = k0 >> 6, d0 = k0 & 63;   // 32-chunk stays inside one head
        const float* Ap = g_Ho + ((size_t)hh * NN + (size_t)nt * 64) * HD + d0;
        const float* Wp = WO + (size_t)ft * 64 * (H * HD) + k0;
        #pragma unroll
        for (int t = tid; t < 512; t += 256) {
            int r = t >> 3, k4 = (t & 7) * 4;
            *(float4*)&As[r * 36 + k4] = *(const float4*)&Ap[(size_t)r * HD + k4];
            *(float4*)&Ws[r * 36 + k4] = *(const float4*)&Wp[(size_t)r * (H * HD) + k4];
        }
        __syncthreads();
        #pragma unroll
        for (int kk = 0; kk < 32; kk += 4) {
            float a[4][4], b[4][4];
            #pragma unroll
            for (int i = 0; i < 4; i++) {
                float4 av = *(const float4*)&As[(tr * 4 + i) * 36 + kk];
                a[i][0] = av.x; a[i][1] = av.y; a[i][2] = av.z; a[i][3] = av.w;
                float4 bv = *(const float4*)&Ws[(tc * 4 + i) * 36 + kk];
                b[i][0] = bv.x; b[i][1] = bv.y; b[i][2] = bv.z; b[i][3] = bv.w;
            }
            #pragma unroll
            for (int u = 0; u < 4; u++)
                #pragma unroll
                for (int i = 0; i < 4; i++)
                    #pragma unroll
                    for (int j = 0; j < 4; j++)
                        acc[i][j] += a[i][u] * b[j][u];
        }
        __syncthreads();
    }
    #pragma unroll
    for (int i = 0; i < 4; i++)
        #pragma unroll
        for (int j = 0; j < 4; j++)
            out[(size_t)(nt * 64 + tr * 4 + i) * FOUT + ft * 64 + tc * 4 + j] = acc[i][j];
}

// ---------------------------------------------------------------------------
extern "C" void kernel_launch(void* const* d_in, const int* in_sizes, int n_in,
                              void* d_out, int out_size) {
    (void)in_sizes; (void)n_in; (void)out_size;
    const float* X    = (const float*)d_in[0];
    const int*   mask = (const int*)d_in[1];
    const float* WQ   = (const float*)d_in[2];
    const float* WK   = (const float*)d_in[3];
    const float* WV   = (const float*)d_in[4];
    const float* WO   = (const float*)d_in[5];
    float* out = (float*)d_out;

    qkv_kernel<<<dim3(NN / 64, H, 3), 256>>>(X, WQ, WK, WV);

    const size_t smem = (size_t)(3 * 128 * PK + 128 * PP + 256) * sizeof(float);  // ~173 KB
    static int attr_set = 0;
    if (!attr_set) {
        cudaFuncSetAttribute(attn_kernel, cudaFuncAttributeMaxDynamicSharedMemorySize, (int)smem);
        attr_set = 1;
    }
    attn_kernel<<<dim3(NN / 128, H), 256, smem>>>(mask);

    oproj_kernel<<<dim3(NN / 64, FOUT / 64), 256>>>(WO, out);
}

// round 4
// speedup vs baseline: 1.5907x; 1.5907x over previous
#include <cuda_runtime.h>

namespace {
constexpr int H    = 8;
constexpr int NN   = 4096;
constexpr int FIN  = 512;
constexpr int HD   = 64;
constexpr int FOUT = 512;
}

typedef unsigned long long ull;

// ---- packed f32x2 helpers (Blackwell FFMA2 path, PTX-only) ----
__device__ __forceinline__ ull fma2(ull a, ull b, ull c) {
    ull d;
    asm("fma.rn.f32x2 %0, %1, %2, %3;" : "=l"(d) : "l"(a), "l"(b), "l"(c));
    return d;
}
__device__ __forceinline__ ull mul2(ull a, ull b) {
    ull d;
    asm("mul.rn.f32x2 %0, %1, %2;" : "=l"(d) : "l"(a), "l"(b));
    return d;
}
__device__ __forceinline__ ull pack2(float x, float y) {
    ull r;
    asm("mov.b64 %0, {%1, %2};" : "=l"(r) : "r"(__float_as_uint(x)), "r"(__float_as_uint(y)));
    return r;
}
__device__ __forceinline__ float2 unpack2(ull v) {
    unsigned lo, hi;
    asm("mov.b64 {%0, %1}, %2;" : "=r"(lo), "=r"(hi) : "l"(v));
    return make_float2(__uint_as_float(lo), __uint_as_float(hi));
}

// Scratch (allocation-free rule: __device__ globals)
__device__ __align__(16) float g_Q [H * NN * HD];
__device__ __align__(16) float g_K [H * NN * HD];
__device__ __align__(16) float g_V [H * NN * HD];
__device__ __align__(16) float g_Ho[H * NN * HD];

// ---------------------------------------------------------------------------
// Kernel 1: Q/K/V projection. out[h,n,d] = sum_f X[h,n,f] * W[h,d,f]
// grid (NN/64, H, 3), block 256. 64x64 tile, 4x4 microtile, BK=32.
// W tile stored k-major (transposed) in smem -> conflict-free b-fragments.
// FFMA2: accumulate col-pairs (b float4 gives natural pairs), dup a.
// ---------------------------------------------------------------------------
__global__ __launch_bounds__(256) void qkv_kernel(
    const float* __restrict__ X, const float* __restrict__ WQ,
    const float* __restrict__ WK, const float* __restrict__ WV) {
    __shared__ float Xs[64 * 36];
    __shared__ float Wt[32 * 68];   // [k][d], stride 68
    const int nt = blockIdx.x, h = blockIdx.y, w = blockIdx.z;
    const float* Wm = (w == 0) ? WQ : (w == 1) ? WK : WV;
    float* out = (w == 0) ? g_Q : (w == 1) ? g_K : g_V;
    const int tid = threadIdx.x, tr = tid >> 4, tc = tid & 15;
    const float* Xp = X + ((size_t)h * NN + (size_t)nt * 64) * FIN;
    const float* Wp = Wm + (size_t)h * HD * FIN;
    ull acc2[4][2] = {};
    for (int k0 = 0; k0 < FIN; k0 += 32) {
        #pragma unroll
        for (int p = 0; p < 2; p++) {
            int t = tid + p * 256;
            int r = t >> 3, k4 = (t & 7) * 4;
            *(float4*)&Xs[r * 36 + k4] = *(const float4*)&Xp[(size_t)r * FIN + k0 + k4];
            float4 wv = *(const float4*)&Wp[(size_t)r * FIN + k0 + k4];
            Wt[(k4 + 0) * 68 + r] = wv.x;
            Wt[(k4 + 1) * 68 + r] = wv.y;
            Wt[(k4 + 2) * 68 + r] = wv.z;
            Wt[(k4 + 3) * 68 + r] = wv.w;
        }
        __syncthreads();
        #pragma unroll
        for (int kk = 0; kk < 32; kk += 4) {
            float4 a[4];
            ulonglong2 b[4];
            #pragma unroll
            for (int i = 0; i < 4; i++)
                a[i] = *(const float4*)&Xs[(tr * 4 + i) * 36 + kk];
            #pragma unroll
            for (int u = 0; u < 4; u++)
                b[u] = *(const ulonglong2*)&Wt[(kk + u) * 68 + tc * 4];
            #pragma unroll
            for (int u = 0; u < 4; u++) {
                #pragma unroll
                for (int i = 0; i < 4; i++) {
                    float av = (u == 0) ? a[i].x : (u == 1) ? a[i].y : (u == 2) ? a[i].z : a[i].w;
                    ull ad = pack2(av, av);
                    acc2[i][0] = fma2(ad, b[u].x, acc2[i][0]);
                    acc2[i][1] = fma2(ad, b[u].y, acc2[i][1]);
                }
            }
        }
        __syncthreads();
    }
    float* op = out + ((size_t)h * NN + (size_t)nt * 64) * HD;
    #pragma unroll
    for (int i = 0; i < 4; i++) {
        float2 lo = unpack2(acc2[i][0]), hi = unpack2(acc2[i][1]);
        *(float4*)&op[(tr * 4 + i) * HD + tc * 4] = make_float4(lo.x, lo.y, hi.x, hi.y);
    }
}

// ---------------------------------------------------------------------------
// Kernel 2: flash attention. 128x128 score tile, block 512 threads, occ 1.
// Q,K stored k-major in smem (transposed): a-frags warp-broadcast, b-frags
// lane-consecutive (conflict-free). Warp owns 8 S-rows -> softmax state in
// registers, reductions via shfl. FFMA2 throughout.
// S map: str=tid>>5 rows str*8..+7; stc=tid&31 cols stc*4..+3.
// PV map: pr=tid>>4 rows pr*4..+3; pd=tid&15 d pd*4..+3 (warp-local rows).
// ---------------------------------------------------------------------------
__global__ __launch_bounds__(512, 1) void attn_kernel(const int* __restrict__ mask) {
    extern __shared__ float sm[];
    float* Qt = sm;                  // [64][132] k-major Q (pre-scaled)
    float* Kt = Qt + 64 * 132;       // [64][132] k-major K
    float* Vs = Kt + 64 * 132;       // [128][64] seq-major V
    float* Ps = Vs + 128 * 64;       // [128][128] mask (int) then P
    int*   Mi = (int*)Ps;

    const int nt = blockIdx.x, h = blockIdx.y;
    const int tid = threadIdx.x;
    const int str = tid >> 5, stc = tid & 31;
    const int pr  = tid >> 4, pd  = tid & 15;
    const int hiHalf = (tid >> 4) & 1;   // 0: PV rows = warp rows 0-3, 1: rows 4-7

    // stage Q transposed, fold 1/sqrt(64)=0.125
    const float* Qp = g_Q + ((size_t)h * NN + (size_t)nt * 128) * HD;
    #pragma unroll
    for (int p = 0; p < 4; p++) {
        int t = tid + p * 512, r = t >> 4, d4 = (t & 15) * 4;
        float4 v = *(const float4*)&Qp[r * HD + d4];
        Qt[(d4 + 0) * 132 + r] = v.x * 0.125f;
        Qt[(d4 + 1) * 132 + r] = v.y * 0.125f;
        Qt[(d4 + 2) * 132 + r] = v.z * 0.125f;
        Qt[(d4 + 3) * 132 + r] = v.w * 0.125f;
    }

    float mrow[8], lrow[8], srow[8];
    #pragma unroll
    for (int i = 0; i < 8; i++) { mrow[i] = -1e30f; lrow[i] = 0.0f; }
    ull o2[4][2] = {};   // PV accum: rows pr*4+i, d-pairs (pd*4)

    const int* mrow_g = mask + ((size_t)h * NN + (size_t)nt * 128) * NN;
    __syncthreads();

    for (int kv0 = 0; kv0 < NN; kv0 += 128) {
        // ---- stage K (transposed), V (natural), mask (into Ps as int) ----
        const float* Kp = g_K + ((size_t)h * NN + kv0) * HD;
        const float* Vp = g_V + ((size_t)h * NN + kv0) * HD;
        #pragma unroll
        for (int p = 0; p < 4; p++) {
            int t = tid + p * 512, r = t >> 4, d4 = (t & 15) * 4;
            float4 kv = *(const float4*)&Kp[r * HD + d4];
            Kt[(d4 + 0) * 132 + r] = kv.x;
            Kt[(d4 + 1) * 132 + r] = kv.y;
            Kt[(d4 + 2) * 132 + r] = kv.z;
            Kt[(d4 + 3) * 132 + r] = kv.w;
            *(float4*)&Vs[r * 64 + d4] = *(const float4*)&Vp[r * HD + d4];
        }
        #pragma unroll
        for (int p = 0; p < 8; p++) {
            int t = tid + p * 512, r = t >> 5, c4 = (t & 31) * 4;
            *(int4*)&Mi[r * 128 + c4] = *(const int4*)&mrow_g[(size_t)r * NN + kv0 + c4];
        }
        __syncthreads();

        // ---- S = Q K^T : acc pairs along rows (a float4 -> natural pairs) ----
        ull sacc[4][4] = {};
        #pragma unroll 4
        for (int k = 0; k < HD; k++) {
            const float* qr = &Qt[k * 132 + str * 8];
            ulonglong2 a01 = *(const ulonglong2*)qr;          // rows 0,1 | 2,3
            ulonglong2 a23 = *(const ulonglong2*)(qr + 4);    // rows 4,5 | 6,7
            float4 bv = *(const float4*)&Kt[k * 132 + stc * 4];
            ull b0 = pack2(bv.x, bv.x), b1 = pack2(bv.y, bv.y);
            ull b2 = pack2(bv.z, bv.z), b3 = pack2(bv.w, bv.w);
            sacc[0][0] = fma2(a01.x, b0, sacc[0][0]);
            sacc[0][1] = fma2(a01.x, b1, sacc[0][1]);
            sacc[0][2] = fma2(a01.x, b2, sacc[0][2]);
            sacc[0][3] = fma2(a01.x, b3, sacc[0][3]);
            sacc[1][0] = fma2(a01.y, b0, sacc[1][0]);
            sacc[1][1] = fma2(a01.y, b1, sacc[1][1]);
            sacc[1][2] = fma2(a01.y, b2, sacc[1][2]);
            sacc[1][3] = fma2(a01.y, b3, sacc[1][3]);
            sacc[2][0] = fma2(a23.x, b0, sacc[2][0]);
            sacc[2][1] = fma2(a23.x, b1, sacc[2][1]);
            sacc[2][2] = fma2(a23.x, b2, sacc[2][2]);
            sacc[2][3] = fma2(a23.x, b3, sacc[2][3]);
            sacc[3][0] = fma2(a23.y, b0, sacc[3][0]);
            sacc[3][1] = fma2(a23.y, b1, sacc[3][1]);
            sacc[3][2] = fma2(a23.y, b2, sacc[3][2]);
            sacc[3][3] = fma2(a23.y, b3, sacc[3][3]);
        }
        // unpack: s[i][j], row i = str*8 + i
        float s[8][4];
        #pragma unroll
        for (int p = 0; p < 4; p++)
            #pragma unroll
            for (int j = 0; j < 4; j++) {
                float2 v = unpack2(sacc[p][j]);
                s[2 * p][j] = v.x; s[2 * p + 1][j] = v.y;
            }

        // ---- mask + warp-local online softmax + P write ----
        #pragma unroll
        for (int i = 0; i < 8; i++) {
            int r = str * 8 + i;
            int4 m = *(const int4*)&Mi[r * 128 + stc * 4];
            if (m.x == 0) s[i][0] = -1e30f;
            if (m.y == 0) s[i][1] = -1e30f;
            if (m.z == 0) s[i][2] = -1e30f;
            if (m.w == 0) s[i][3] = -1e30f;
            float mx = fmaxf(fmaxf(s[i][0], s[i][1]), fmaxf(s[i][2], s[i][3]));
            #pragma unroll
            for (int off = 16; off; off >>= 1)
                mx = fmaxf(mx, __shfl_xor_sync(0xffffffffu, mx, off));
            float mnew = fmaxf(mrow[i], mx);
            float e0 = __expf(s[i][0] - mnew), e1 = __expf(s[i][1] - mnew);
            float e2 = __expf(s[i][2] - mnew), e3 = __expf(s[i][3] - mnew);
            float sum = (e0 + e1) + (e2 + e3);
            #pragma unroll
            for (int off = 16; off; off >>= 1)
                sum += __shfl_xor_sync(0xffffffffu, sum, off);
            float sc = __expf(mrow[i] - mnew);
            lrow[i] = lrow[i] * sc + sum;
            mrow[i] = mnew;
            srow[i] = sc;
            *(float4*)&Ps[r * 128 + stc * 4] = make_float4(e0, e1, e2, e3);
        }
        __syncwarp();   // P rows are warp-local; warp-level visibility suffices

        // ---- rescale O, then O += P @ V ----
        #pragma unroll
        for (int i = 0; i < 4; i++) {
            float sc = hiHalf ? srow[4 + i] : srow[i];
            ull sc2 = pack2(sc, sc);
            o2[i][0] = mul2(o2[i][0], sc2);
            o2[i][1] = mul2(o2[i][1], sc2);
        }
        #pragma unroll 2
        for (int k = 0; k < 128; k += 4) {
            float4 p4[4];
            ulonglong2 v2[4];
            #pragma unroll
            for (int i = 0; i < 4; i++)
                p4[i] = *(const float4*)&Ps[(pr * 4 + i) * 128 + k];
            #pragma unroll
            for (int u = 0; u < 4; u++)
                v2[u] = *(const ulonglong2*)&Vs[(k + u) * 64 + pd * 4];
            #pragma unroll
            for (int u = 0; u < 4; u++) {
                #pragma unroll
                for (int i = 0; i < 4; i++) {
                    float pv = (u == 0) ? p4[i].x : (u == 1) ? p4[i].y : (u == 2) ? p4[i].z : p4[i].w;
                    ull pd2 = pack2(pv, pv);
                    o2[i][0] = fma2(pd2, v2[u].x, o2[i][0]);
                    o2[i][1] = fma2(pd2, v2[u].y, o2[i][1]);
                }
            }
        }
        __syncthreads();   // protect Kt/Vs/Ps(mask) before next staging
    }

    // ---- finalize: /l, write Hout ----
    float* Op = g_Ho + ((size_t)h * NN + (size_t)nt * 128) * HD;
    #pragma unroll
    for (int i = 0; i < 4; i++) {
        float li = hiHalf ? lrow[4 + i] : lrow[i];
        float linv = 1.0f / li;
        float2 lo = unpack2(o2[i][0]), hi = unpack2(o2[i][1]);
        *(float4*)&Op[(pr * 4 + i) * HD + pd * 4] =
            make_float4(lo.x * linv, lo.y * linv, hi.x * linv, hi.y * linv);
    }
}

// ---------------------------------------------------------------------------
// Kernel 3: output projection. out[n,fo] = sum_{h,d} Ho[h,n,d] * WO[fo, h*64+d]
// Same transposed-W + FFMA2 structure as qkv. grid (NN/64, FOUT/64), block 256.
// ---------------------------------------------------------------------------
__global__ __launch_bounds__(256) void oproj_kernel(
    const float* __restrict__ WO, float* __restrict__ out) {
    __shared__ float As[64 * 36];
    __shared__ float Wt[32 * 68];
    const int nt = blockIdx.x, ft = blockIdx.y;
    const int tid = threadIdx.x, tr = tid >> 4, tc = tid & 15;
    ull acc2[4][2] = {};
    for (int k0 = 0; k0 < H * HD; k0 += 32) {
        const int hh = k0 >> 6, d0 = k0 & 63;   // 32-chunk stays inside one head
        const float* Ap = g_Ho + ((size_t)hh * NN + (size_t)nt * 64) * HD + d0;
        const float* Wp = WO + (size_t)ft * 64 * (H * HD) + k0;
        #pragma unroll
        for (int p = 0; p < 2; p++) {
            int t = tid + p * 256;
            int r = t >> 3, k4 = (t & 7) * 4;
            *(float4*)&As[r * 36 + k4] = *(const float4*)&Ap[(size_t)r * HD + k4];
            float4 wv = *(const float4*)&Wp[(size_t)r * (H * HD) + k4];
            Wt[(k4 + 0) * 68 + r] = wv.x;
            Wt[(k4 + 1) * 68 + r] = wv.y;
            Wt[(k4 + 2) * 68 + r] = wv.z;
            Wt[(k4 + 3) * 68 + r] = wv.w;
        }
        __syncthreads();
        #pragma unroll
        for (int kk = 0; kk < 32; kk += 4) {
            float4 a[4];
            ulonglong2 b[4];
            #pragma unroll
            for (int i = 0; i < 4; i++)
                a[i] = *(const float4*)&As[(tr * 4 + i) * 36 + kk];
            #pragma unroll
            for (int u = 0; u < 4; u++)
                b[u] = *(const ulonglong2*)&Wt[(kk + u) * 68 + tc * 4];
            #pragma unroll
            for (int u = 0; u < 4; u++) {
                #pragma unroll
                for (int i = 0; i < 4; i++) {
                    float av = (u == 0) ? a[i].x : (u == 1) ? a[i].y : (u == 2) ? a[i].z : a[i].w;
                    ull ad = pack2(av, av);
                    acc2[i][0] = fma2(ad, b[u].x, acc2[i][0]);
                    acc2[i][1] = fma2(ad, b[u].y, acc2[i][1]);
                }
            }
        }
        __syncthreads();
    }
    #pragma unroll
    for (int i = 0; i < 4; i++) {
        float2 lo = unpack2(acc2[i][0]), hi = unpack2(acc2[i][1]);
        *(float4*)&out[(size_t)(nt * 64 + tr * 4 + i) * FOUT + ft * 64 + tc * 4] =
            make_float4(lo.x, lo.y, hi.x, hi.y);
    }
}

// ---------------------------------------------------------------------------
extern "C" void kernel_launch(void* const* d_in, const int* in_sizes, int n_in,
                              void* d_out, int out_size) {
    (void)in_sizes; (void)n_in; (void)out_size;
    const float* X    = (const float*)d_in[0];
    const int*   mask = (const int*)d_in[1];
    const float* WQ   = (const float*)d_in[2];
    const float* WK   = (const float*)d_in[3];
    const float* WV   = (const float*)d_in[4];
    const float* WO   = (const float*)d_in[5];
    float* out = (float*)d_out;

    qkv_kernel<<<dim3(NN / 64, H, 3), 256>>>(X, WQ, WK, WV);

    const size_t smem = (size_t)(64 * 132 * 2 + 128 * 64 + 128 * 128) * sizeof(float);  // ~162 KB
    cudaFuncSetAttribute(attn_kernel, cudaFuncAttributeMaxDynamicSharedMemorySize, (int)smem);
    attn_kernel<<<dim3(NN / 128, H), 512, smem>>>(mask);

    oproj_kernel<<<dim3(NN / 64, FOUT / 64), 256>>>(WO, out);
}